// round 2
// baseline (speedup 1.0000x reference)
#include <cuda_runtime.h>
#include <cstdint>
#include <math.h>

// ---------------- problem dims ----------------
#define BN  256   // B*N patches
#define AD  98    // angular atoms
#define MD  128   // spatial atoms
#define CD  16    // spectral atoms
#define CHD 8     // spectral channels
#define STD 64    // S*T
#define UVD 49    // U*V

#define NPAM (BN*AD*MD)          // 3,211,264  (p,a,m) triples
#define VSZ  (AD*MD*CD)          // 200,704 single-patch code size

// ---------------- device-global scratch (no allocs allowed) ----------------
__device__ float g_Z [51380224];   // z      (BN,A,M,C)
__device__ float g_Y [51380224];   // y_k    (BN,A,M,C)
__device__ float g_P1[25690112];   // (BN,A,M,CH)   recon step1 / adjoint step2
__device__ float g_P2[12845056];   // (BN,A,ST,CH)  recon step2 / adjoint step1
__device__ float g_R [6422528];    // residual (BN,UV,ST,CH)
__device__ float g_v [200704];     // power-iter vector
__device__ float g_w [200704];
__device__ float g_t1e[200704];
__device__ float g_t2e[200704];
__device__ float g_Ga[9604];       // 98x98
__device__ float g_Gs[16384];      // 128x128
__device__ float g_Gc[256];        // 16x16
__device__ float g_nrm;
__device__ float g_step;
__device__ float g_thr;

// ---------------- small utility kernels ----------------
__global__ void k_gram(const float* __restrict__ d, float* __restrict__ g, int n, int k) {
    int i = blockIdx.x * blockDim.x + threadIdx.x;
    if (i >= n * n) return;
    int r = i / n, c = i % n;
    float acc = 0.f;
    for (int j = 0; j < k; j++) acc += d[r * k + j] * d[c * k + j];
    g[i] = acc;
}

__device__ __forceinline__ unsigned rotl32(unsigned x, int r) { return (x << r) | (x >> (32 - r)); }

__device__ __forceinline__ float bits_to_normal(unsigned b) {
    // JAX: uniform in [lo, 1) with lo = nextafter(-1,0); then sqrt(2)*erfinv(u)
    float f = __uint_as_float((b >> 9) | 0x3f800000u) - 1.0f;   // [0,1)
    const float lo = -0.99999994f;
    float u = fmaxf(lo, f * 2.0f + lo);                         // (hi - lo) rounds to 2.0f
    return 1.4142135f * erfinvf(u);
}

// v0 = jax.random.normal(key(42), (A,M,C)) via PARTITIONABLE threefry:
// per element i: counts = iota(uint64) -> (hi,lo) = (0, i);
// (y0,y1) = threefry2x32((0,42), (0,i)); 32-bit output = y0 ^ y1.
__global__ void k_v0() {
    int i = blockIdx.x * blockDim.x + threadIdx.x;
    if (i >= VSZ) return;
    unsigned x0 = 0u, x1 = (unsigned)i;
    const unsigned ks0 = 0u, ks1 = 42u, ks2 = 0u ^ 42u ^ 0x1BD11BDAu;
    x0 += ks0; x1 += ks1;
#define TFR(r) { x0 += x1; x1 = rotl32(x1, r); x1 ^= x0; }
    TFR(13) TFR(15) TFR(26) TFR(6)
    x0 += ks1; x1 += ks2 + 1u;
    TFR(17) TFR(29) TFR(16) TFR(24)
    x0 += ks2; x1 += ks0 + 2u;
    TFR(13) TFR(15) TFR(26) TFR(6)
    x0 += ks0; x1 += ks1 + 3u;
    TFR(17) TFR(29) TFR(16) TFR(24)
    x0 += ks1; x1 += ks2 + 4u;
    TFR(13) TFR(15) TFR(26) TFR(6)
    x0 += ks2; x1 += ks0 + 5u;
#undef TFR
    g_v[i] = bits_to_normal(x0 ^ x1);
}

// deterministic single-block L2-norm -> g_nrm
__global__ void k_norm(const float* __restrict__ src, int n) {
    __shared__ float s[1024];
    int t = threadIdx.x;
    float acc = 0.f;
    for (int i = t; i < n; i += 1024) { float v = src[i]; acc += v * v; }
    s[t] = acc; __syncthreads();
    for (int o = 512; o > 0; o >>= 1) { if (t < o) s[t] += s[t + o]; __syncthreads(); }
    if (t == 0) g_nrm = sqrtf(s[0]);
}

__global__ void k_scale(const float* __restrict__ src, float* __restrict__ dst, int n, float eps) {
    int i = blockIdx.x * blockDim.x + threadIdx.x;
    if (i < n) dst[i] = src[i] / (g_nrm + eps);
}

// ---- power-iteration mode products on a single (A,M,C) tensor ----
__global__ void k_eig_c() {  // t1[a,m,d] = sum_c v[a,m,c] Gc[c,d]
    int tid = blockIdx.x * blockDim.x + threadIdx.x;
    if (tid >= AD * MD) return;
    float vv[16];
    const float4* vp = reinterpret_cast<const float4*>(g_v) + tid * 4;
    float4 a0 = vp[0], a1 = vp[1], a2 = vp[2], a3 = vp[3];
    vv[0]=a0.x; vv[1]=a0.y; vv[2]=a0.z; vv[3]=a0.w;
    vv[4]=a1.x; vv[5]=a1.y; vv[6]=a1.z; vv[7]=a1.w;
    vv[8]=a2.x; vv[9]=a2.y; vv[10]=a2.z; vv[11]=a2.w;
    vv[12]=a3.x; vv[13]=a3.y; vv[14]=a3.z; vv[15]=a3.w;
    #pragma unroll
    for (int d = 0; d < 16; d++) {
        float acc = 0.f;
        #pragma unroll
        for (int c = 0; c < 16; c++) acc += vv[c] * g_Gc[c * 16 + d];
        g_t1e[tid * 16 + d] = acc;
    }
}
__global__ void k_eig_s() {  // t2[a,n,d] = sum_m t1[a,m,d] Gs[m,n]
    int tid = blockIdx.x * blockDim.x + threadIdx.x;
    if (tid >= VSZ) return;
    int d = tid & 15, n = (tid >> 4) & 127, a = tid >> 11;
    float acc = 0.f;
    for (int m = 0; m < 128; m++) acc += g_t1e[((a << 7) + m) * 16 + d] * g_Gs[(m << 7) + n];
    g_t2e[tid] = acc;
}
__global__ void k_eig_a() {  // w[b,n,d] = sum_a t2[a,n,d] Ga[a,b]
    int tid = blockIdx.x * blockDim.x + threadIdx.x;
    if (tid >= VSZ) return;
    int d = tid & 15, n = (tid >> 4) & 127, b = tid >> 11;
    float acc = 0.f;
    for (int a = 0; a < 98; a++) acc += g_t2e[((a << 7) + n) * 16 + d] * g_Ga[a * 98 + b];
    g_w[tid] = acc;
}
__global__ void k_finalize() {
    float L = fmaxf(g_nrm, 1e-6f);
    g_step = 1.0f / L;
    g_thr  = 0.1f / L;
}

// ---------------- FISTA main kernels ----------------
// K1: P1[p,a,m,h] = sum_c Z[p,a,m,c] * Dc[c,h]
__global__ void k_recon_c(const float* __restrict__ zin, float* __restrict__ out,
                          const float* __restrict__ dc) {
    __shared__ float sdc[128];
    int t = threadIdx.x;
    if (t < 128) sdc[t] = dc[t];
    __syncthreads();
    int tid = blockIdx.x * blockDim.x + t;
    if (tid >= NPAM) return;
    const float4* zp = reinterpret_cast<const float4*>(zin) + (size_t)tid * 4;
    float z[16];
    float4 a0 = zp[0], a1 = zp[1], a2 = zp[2], a3 = zp[3];
    z[0]=a0.x; z[1]=a0.y; z[2]=a0.z; z[3]=a0.w;
    z[4]=a1.x; z[5]=a1.y; z[6]=a1.z; z[7]=a1.w;
    z[8]=a2.x; z[9]=a2.y; z[10]=a2.z; z[11]=a2.w;
    z[12]=a3.x; z[13]=a3.y; z[14]=a3.z; z[15]=a3.w;
    float r[8];
    #pragma unroll
    for (int h = 0; h < 8; h++) r[h] = 0.f;
    #pragma unroll
    for (int c = 0; c < 16; c++)
        #pragma unroll
        for (int h = 0; h < 8; h++) r[h] += z[c] * sdc[c * 8 + h];
    float4* op = reinterpret_cast<float4*>(out) + (size_t)tid * 2;
    op[0] = make_float4(r[0], r[1], r[2], r[3]);
    op[1] = make_float4(r[4], r[5], r[6], r[7]);
}

// K2: P2[p,a,st,h] = sum_m P1[p,a,m,h] * Ds[m,st]   (block = (p, a-chunk of 14))
__global__ void k_recon_m(const float* __restrict__ in, float* __restrict__ out,
                          const float* __restrict__ ds) {
    __shared__ float sds[MD * STD];   // 32 KB
    __shared__ float sin_[MD * CHD];  // 4 KB
    int p = blockIdx.x, ac = blockIdx.y;
    int t = threadIdx.x;  // 512
    for (int i = t; i < MD * STD; i += 512) sds[i] = ds[i];
    int st = t >> 3, h = t & 7;
    for (int aa = 0; aa < 14; aa++) {
        int a = ac * 14 + aa;
        __syncthreads();
        const float* src = in + (size_t)(p * 98 + a) * 1024;
        for (int i = t; i < 1024; i += 512) sin_[i] = src[i];
        __syncthreads();
        float acc = 0.f;
        #pragma unroll 8
        for (int m = 0; m < 128; m++) acc += sin_[m * 8 + h] * sds[m * 64 + st];
        out[(size_t)(p * 98 + a) * 512 + t] = acc;   // st*8+h == t
    }
}

// K3: R[p,uv,st,h] = sum_a Da[a,uv]*P2[p,a,st,h]  (- x if subx)
__global__ void k_recon_a(const float* __restrict__ in, const float* __restrict__ x,
                          float* __restrict__ out, const float* __restrict__ da, int subx) {
    __shared__ float sda[AD * UVD];   // 19.2 KB
    int p = blockIdx.x, t = threadIdx.x;  // 512 threads = sth
    for (int i = t; i < AD * UVD; i += 512) sda[i] = da[i];
    __syncthreads();
    float acc[49];
    #pragma unroll
    for (int uv = 0; uv < 49; uv++) acc[uv] = 0.f;
    const float* src = in + (size_t)p * 98 * 512;
    for (int a = 0; a < 98; a++) {
        float v = __ldg(src + a * 512 + t);
        #pragma unroll
        for (int uv = 0; uv < 49; uv++) acc[uv] += v * sda[a * 49 + uv];
    }
    size_t base = (size_t)p * 49 * 512;
    if (subx) {
        #pragma unroll
        for (int uv = 0; uv < 49; uv++)
            out[base + uv * 512 + t] = acc[uv] - x[base + uv * 512 + t];
    } else {
        #pragma unroll
        for (int uv = 0; uv < 49; uv++)
            out[base + uv * 512 + t] = acc[uv];
    }
}

// K4: Q1[p,a,st,h] = sum_uv Da[a,uv] * (sgn * src[p,uv,st,h])
__global__ void k_adj_a(const float* __restrict__ src, float* __restrict__ out,
                        const float* __restrict__ da, float sgn) {
    extern __shared__ float sm[];                 // [49*512] R  + [4802] Da
    float* sR = sm;
    float* sDa = sm + UVD * 512;
    int p = blockIdx.x, t = threadIdx.x;          // 512
    const float* rp = src + (size_t)p * UVD * 512;
    for (int i = t; i < UVD * 512; i += 512) sR[i] = sgn * rp[i];
    for (int i = t; i < AD * UVD; i += 512) sDa[i] = da[i];
    __syncthreads();
    for (int a = 0; a < 98; a++) {
        float acc = 0.f;
        #pragma unroll
        for (int uv = 0; uv < 49; uv++) acc += sDa[a * 49 + uv] * sR[uv * 512 + t];
        out[(size_t)p * 98 * 512 + a * 512 + t] = acc;
    }
}

// K5: Q2[p,a,m,h] = sum_st Ds[m,st] * Q1[p,a,st,h]
__global__ void k_adj_m(const float* __restrict__ in, float* __restrict__ out,
                        const float* __restrict__ ds) {
    __shared__ float sds[MD * 65];   // padded: 33.3 KB
    __shared__ float sin_[STD * CHD];
    int p = blockIdx.x, ac = blockIdx.y, t = threadIdx.x;  // 512
    for (int i = t; i < MD * STD; i += 512) { int m = i >> 6, st = i & 63; sds[m * 65 + st] = ds[i]; }
    for (int aa = 0; aa < 14; aa++) {
        int a = ac * 14 + aa;
        __syncthreads();
        const float* src = in + (size_t)(p * 98 + a) * 512;
        sin_[t] = src[t];
        __syncthreads();
        #pragma unroll
        for (int k = 0; k < 2; k++) {
            int o = t + k * 512;
            int m = o >> 3, h = o & 7;
            float acc = 0.f;
            #pragma unroll
            for (int st = 0; st < 64; st++) acc += sds[m * 65 + st] * sin_[st * 8 + h];
            out[(size_t)(p * 98 + a) * 1024 + o] = acc;
        }
    }
}

// K6: g[c] = sum_h Q2[..h]*Dc[c,h];  zn = soft(y - step*g, thr);  y = zn + mom*(zn - z); z = zn
__global__ void k_update(const float* __restrict__ q2, const float* __restrict__ dc,
                         float mom, int first) {
    __shared__ float sdc[128];
    int t = threadIdx.x;
    if (t < 128) sdc[t] = dc[t];
    __syncthreads();
    int tid = blockIdx.x * blockDim.x + t;
    if (tid >= NPAM) return;
    const float4* qp = reinterpret_cast<const float4*>(q2) + (size_t)tid * 2;
    float4 q0 = qp[0], q1 = qp[1];
    float q[8] = {q0.x, q0.y, q0.z, q0.w, q1.x, q1.y, q1.z, q1.w};
    float step = g_step, thr = g_thr;
    float4* zp = reinterpret_cast<float4*>(g_Z) + (size_t)tid * 4;
    float4* yp = reinterpret_cast<float4*>(g_Y) + (size_t)tid * 4;
    #pragma unroll
    for (int j = 0; j < 4; j++) {
        float4 yv, zv;
        if (first) { yv = make_float4(0.f, 0.f, 0.f, 0.f); zv = yv; }
        else       { yv = yp[j]; zv = zp[j]; }
        float yin[4] = {yv.x, yv.y, yv.z, yv.w};
        float zin[4] = {zv.x, zv.y, zv.z, zv.w};
        float znv[4], ynv[4];
        #pragma unroll
        for (int k = 0; k < 4; k++) {
            int c = j * 4 + k;
            float g = 0.f;
            #pragma unroll
            for (int h = 0; h < 8; h++) g += q[h] * sdc[c * 8 + h];
            float v = yin[k] - step * g;
            float av = fabsf(v) - thr;
            float zn = (av > 0.f) ? copysignf(av, v) : 0.f;
            znv[k] = zn;
            ynv[k] = zn + mom * (zn - zin[k]);
        }
        zp[j] = make_float4(znv[0], znv[1], znv[2], znv[3]);
        yp[j] = make_float4(ynv[0], ynv[1], ynv[2], ynv[3]);
    }
}

// ---------------- host launch ----------------
extern "C" void kernel_launch(void* const* d_in, const int* in_sizes, int n_in,
                              void* d_out, int out_size) {
    const float* x  = (const float*)d_in[0];
    const float* da = (const float*)d_in[1];
    const float* ds = (const float*)d_in[2];
    const float* dc = (const float*)d_in[3];
    float* out = (float*)d_out;

    void *pGa, *pGs, *pGc, *pv, *pw, *pZ, *pY, *pP1, *pP2, *pR;
    cudaGetSymbolAddress(&pGa, g_Ga);
    cudaGetSymbolAddress(&pGs, g_Gs);
    cudaGetSymbolAddress(&pGc, g_Gc);
    cudaGetSymbolAddress(&pv,  g_v);
    cudaGetSymbolAddress(&pw,  g_w);
    cudaGetSymbolAddress(&pZ,  g_Z);
    cudaGetSymbolAddress(&pY,  g_Y);
    cudaGetSymbolAddress(&pP1, g_P1);
    cudaGetSymbolAddress(&pP2, g_P2);
    cudaGetSymbolAddress(&pR,  g_R);

    size_t smem4 = (size_t)(UVD * 512 + AD * UVD) * sizeof(float);  // 119,560 B
    cudaFuncSetAttribute(k_adj_a, cudaFuncAttributeMaxDynamicSharedMemorySize, (int)smem4);

    // --- Gram matrices ---
    k_gram<<<(9604  + 255) / 256, 256>>>(da, (float*)pGa, 98, 49);
    k_gram<<<(16384 + 255) / 256, 256>>>(ds, (float*)pGs, 128, 64);
    k_gram<<<1, 256>>>(dc, (float*)pGc, 16, 8);

    // --- v0 and power iteration for L ---
    k_v0<<<(VSZ + 255) / 256, 256>>>();
    k_norm<<<1, 1024>>>((const float*)pv, VSZ);
    k_scale<<<VSZ / 256, 256>>>((const float*)pv, (float*)pv, VSZ, 0.f);
    for (int it = 0; it < 10; ++it) {
        k_eig_c<<<(AD * MD + 255) / 256, 256>>>();
        k_eig_s<<<VSZ / 256, 256>>>();
        k_eig_a<<<VSZ / 256, 256>>>();
        k_norm<<<1, 1024>>>((const float*)pw, VSZ);
        k_scale<<<VSZ / 256, 256>>>((const float*)pw, (float*)pv, VSZ, 1e-12f);
    }
    k_finalize<<<1, 1>>>();

    // --- momentum schedule (data-independent) ---
    float mom[15]; float tmom = 1.f;
    for (int i = 0; i < 15; i++) {
        float tn = (1.f + sqrtf(1.f + 4.f * tmom * tmom)) * 0.5f;
        mom[i] = (tmom - 1.f) / tn;
        tmom = tn;
    }

    const int G6 = NPAM / 256;  // 12544

    // --- FISTA iteration 1: y=z=0 -> g = -adj(x), no recon needed, no state zeroing ---
    k_adj_a<<<256, 512, smem4>>>(x, (float*)pP2, da, -1.f);
    k_adj_m<<<dim3(256, 7), 512>>>((const float*)pP2, (float*)pP1, ds);
    k_update<<<G6, 256>>>((const float*)pP1, dc, mom[0], 1);

    // --- FISTA iterations 2..15 ---
    for (int it = 1; it < 15; ++it) {
        k_recon_c<<<G6, 256>>>((const float*)pY, (float*)pP1, dc);
        k_recon_m<<<dim3(256, 7), 512>>>((const float*)pP1, (float*)pP2, ds);
        k_recon_a<<<256, 512>>>((const float*)pP2, x, (float*)pR, da, 1);
        k_adj_a<<<256, 512, smem4>>>((const float*)pR, (float*)pP2, da, 1.f);
        k_adj_m<<<dim3(256, 7), 512>>>((const float*)pP2, (float*)pP1, ds);
        k_update<<<G6, 256>>>((const float*)pP1, dc, mom[it], 0);
    }

    // --- final reconstruction into d_out (layout matches (b,n,u,v,s,t,ch)) ---
    k_recon_c<<<G6, 256>>>((const float*)pZ, (float*)pP1, dc);
    k_recon_m<<<dim3(256, 7), 512>>>((const float*)pP1, (float*)pP2, ds);
    k_recon_a<<<256, 512>>>((const float*)pP2, nullptr, out, da, 0);
}

// round 4
// speedup vs baseline: 1.1579x; 1.1579x over previous
#include <cuda_runtime.h>
#include <math.h>

// ---------------- problem dims ----------------
#define BN  256
#define AD  98
#define MD  128
#define CD  16
#define CHD 8
#define STD 64
#define UVD 49
#define VSZ (AD*MD*CD)          // 200,704

// ---------------- device-global scratch ----------------
__device__ float g_Z    [51380224];   // (p,a,m,c)
__device__ float g_Y    [51380224];   // (p,a,m,c)
__device__ float g_P2   [12845056];   // (p,a,st,h)
__device__ float g_P2b  [12845056];   // (p,a,st,h)
__device__ float g_AdjX1[12845056];   // (p,a,st,h)  = Da^T x  (precomputed once)
__device__ float g_v [VSZ];
__device__ float g_w [VSZ];
__device__ float g_t1e[VSZ];
__device__ float g_t2e[VSZ];
__device__ float g_Ga[9604];
__device__ float g_Gs[16384];
__device__ float g_Gc[256];
__device__ float g_nrm;
__device__ float g_step;
__device__ float g_thr;

// ---------------- setup kernels (unchanged from passing R2) ----------------
__global__ void k_gram(const float* __restrict__ d, float* __restrict__ g, int n, int k) {
    int i = blockIdx.x * blockDim.x + threadIdx.x;
    if (i >= n * n) return;
    int r = i / n, c = i % n;
    float acc = 0.f;
    for (int j = 0; j < k; j++) acc += d[r * k + j] * d[c * k + j];
    g[i] = acc;
}

__device__ __forceinline__ unsigned rotl32(unsigned x, int r) { return (x << r) | (x >> (32 - r)); }

__device__ __forceinline__ float bits_to_normal(unsigned b) {
    float f = __uint_as_float((b >> 9) | 0x3f800000u) - 1.0f;
    const float lo = -0.99999994f;
    float u = fmaxf(lo, f * 2.0f + lo);
    return 1.4142135f * erfinvf(u);
}

// partitionable threefry: per element i, (y0,y1)=threefry2x32((0,42),(0,i)); out = y0^y1
__global__ void k_v0() {
    int i = blockIdx.x * blockDim.x + threadIdx.x;
    if (i >= VSZ) return;
    unsigned x0 = 0u, x1 = (unsigned)i;
    const unsigned ks0 = 0u, ks1 = 42u, ks2 = 0u ^ 42u ^ 0x1BD11BDAu;
    x0 += ks0; x1 += ks1;
#define TFR(r) { x0 += x1; x1 = rotl32(x1, r); x1 ^= x0; }
    TFR(13) TFR(15) TFR(26) TFR(6)
    x0 += ks1; x1 += ks2 + 1u;
    TFR(17) TFR(29) TFR(16) TFR(24)
    x0 += ks2; x1 += ks0 + 2u;
    TFR(13) TFR(15) TFR(26) TFR(6)
    x0 += ks0; x1 += ks1 + 3u;
    TFR(17) TFR(29) TFR(16) TFR(24)
    x0 += ks1; x1 += ks2 + 4u;
    TFR(13) TFR(15) TFR(26) TFR(6)
    x0 += ks2; x1 += ks0 + 5u;
#undef TFR
    g_v[i] = bits_to_normal(x0 ^ x1);
}

__global__ void k_norm(const float* __restrict__ src, int n) {
    __shared__ float s[1024];
    int t = threadIdx.x;
    float acc = 0.f;
    for (int i = t; i < n; i += 1024) { float v = src[i]; acc += v * v; }
    s[t] = acc; __syncthreads();
    for (int o = 512; o > 0; o >>= 1) { if (t < o) s[t] += s[t + o]; __syncthreads(); }
    if (t == 0) g_nrm = sqrtf(s[0]);
}

__global__ void k_scale(const float* __restrict__ src, float* __restrict__ dst, int n, float eps) {
    int i = blockIdx.x * blockDim.x + threadIdx.x;
    if (i < n) dst[i] = src[i] / (g_nrm + eps);
}

__global__ void k_eig_c() {
    int tid = blockIdx.x * blockDim.x + threadIdx.x;
    if (tid >= AD * MD) return;
    float vv[16];
    const float4* vp = reinterpret_cast<const float4*>(g_v) + tid * 4;
    float4 a0 = vp[0], a1 = vp[1], a2 = vp[2], a3 = vp[3];
    vv[0]=a0.x; vv[1]=a0.y; vv[2]=a0.z; vv[3]=a0.w;
    vv[4]=a1.x; vv[5]=a1.y; vv[6]=a1.z; vv[7]=a1.w;
    vv[8]=a2.x; vv[9]=a2.y; vv[10]=a2.z; vv[11]=a2.w;
    vv[12]=a3.x; vv[13]=a3.y; vv[14]=a3.z; vv[15]=a3.w;
    #pragma unroll
    for (int d = 0; d < 16; d++) {
        float acc = 0.f;
        #pragma unroll
        for (int c = 0; c < 16; c++) acc += vv[c] * g_Gc[c * 16 + d];
        g_t1e[tid * 16 + d] = acc;
    }
}
__global__ void k_eig_s() {
    int tid = blockIdx.x * blockDim.x + threadIdx.x;
    if (tid >= VSZ) return;
    int d = tid & 15, n = (tid >> 4) & 127, a = tid >> 11;
    float acc = 0.f;
    for (int m = 0; m < 128; m++) acc += g_t1e[((a << 7) + m) * 16 + d] * g_Gs[(m << 7) + n];
    g_t2e[tid] = acc;
}
__global__ void k_eig_a() {
    int tid = blockIdx.x * blockDim.x + threadIdx.x;
    if (tid >= VSZ) return;
    int d = tid & 15, n = (tid >> 4) & 127, b = tid >> 11;
    float acc = 0.f;
    for (int a = 0; a < 98; a++) acc += g_t2e[((a << 7) + n) * 16 + d] * g_Ga[a * 98 + b];
    g_w[tid] = acc;
}
__global__ void k_finalize() {
    float L = fmaxf(g_nrm, 1e-6f);
    g_step = 1.0f / L;
    g_thr  = 0.1f / L;
}

// K_adjx: Q[p,a,st,h] = sum_uv Da[a,uv] * x[p,uv,st,h]    (runs once)
__global__ void k_adj_a(const float* __restrict__ src, float* __restrict__ out,
                        const float* __restrict__ da) {
    extern __shared__ float sm[];                 // [49*512] + [98*49]
    float* sR = sm;
    float* sDa = sm + UVD * 512;
    int p = blockIdx.x, t = threadIdx.x;          // 512
    const float* rp = src + (size_t)p * UVD * 512;
    for (int i = t; i < UVD * 512; i += 512) sR[i] = rp[i];
    for (int i = t; i < AD * UVD; i += 512) sDa[i] = da[i];
    __syncthreads();
    for (int a = 0; a < AD; a++) {
        float acc = 0.f;
        #pragma unroll
        for (int uv = 0; uv < UVD; uv++) acc += sDa[a * UVD + uv] * sR[uv * 512 + t];
        out[(size_t)p * AD * 512 + a * 512 + t] = acc;
    }
}

// final uv expansion: out[p,uv,st,h] = sum_a Da[a,uv] * P2[p,a,st,h]   (runs once)
__global__ void k_recon_a(const float* __restrict__ in, float* __restrict__ out,
                          const float* __restrict__ da) {
    __shared__ float sda[AD * UVD];
    int p = blockIdx.x, t = threadIdx.x;
    for (int i = t; i < AD * UVD; i += 512) sda[i] = da[i];
    __syncthreads();
    float acc[UVD];
    #pragma unroll
    for (int uv = 0; uv < UVD; uv++) acc[uv] = 0.f;
    const float* src = in + (size_t)p * AD * 512;
    for (int a = 0; a < AD; a++) {
        float v = __ldg(src + a * 512 + t);
        #pragma unroll
        for (int uv = 0; uv < UVD; uv++) acc[uv] += v * sda[a * UVD + uv];
    }
    size_t base = (size_t)p * UVD * 512;
    #pragma unroll
    for (int uv = 0; uv < UVD; uv++)
        out[base + uv * 512 + t] = acc[uv];
}

// ---------------- fused FISTA kernels ----------------
// kA: P2[p,a,st,h] = sum_m ( sum_c Y[p,a,m,c] Dc[c,h] ) Ds[m,st]
// dyn smem: sDs[8192] | sDc[128] | sY[4*2048] | sP1[4*8*129]
#define KA_SDS   0
#define KA_SDC   8192
#define KA_SY    8320
#define KA_SP1   (8320 + 8192)
#define KA_SMEM  ((KA_SP1 + 4*8*129) * 4)     // floats*4 bytes = 82,560 B
__global__ void __launch_bounds__(512, 2)
kA_recon(const float* __restrict__ yin, const float* __restrict__ ds,
         const float* __restrict__ dc, float* __restrict__ p2) {
    extern __shared__ float sm[];
    float* sDs = sm + KA_SDS;
    float* sDc = sm + KA_SDC;
    float* sY  = sm + KA_SY;
    float* sP1 = sm + KA_SP1;
    int p = blockIdx.x, a0 = blockIdx.y * 4;
    int ab = min(4, AD - a0);
    int t = threadIdx.x;
    for (int i = t; i < MD * STD; i += 512) sDs[i] = ds[i];
    if (t < 128) sDc[t] = dc[t];
    for (int i = t; i < ab * 2048; i += 512) {
        int al = i >> 11, j = i & 2047;
        sY[al * 2048 + j] = yin[((size_t)(p * AD + a0 + al)) * 2048 + j];
    }
    __syncthreads();
    // stage 1: c-contraction -> sP1[al][h][129-padded m]
    {
        int al = t >> 7, m = t & 127;
        if (al < ab) {
            const float4* yv = reinterpret_cast<const float4*>(sY + al * 2048 + m * 16);
            float4 y0 = yv[0], y1 = yv[1], y2 = yv[2], y3 = yv[3];
            float yy[16] = {y0.x,y0.y,y0.z,y0.w, y1.x,y1.y,y1.z,y1.w,
                            y2.x,y2.y,y2.z,y2.w, y3.x,y3.y,y3.z,y3.w};
            float r[8];
            #pragma unroll
            for (int h = 0; h < 8; h++) r[h] = 0.f;
            const float4* dc4 = reinterpret_cast<const float4*>(sDc);
            #pragma unroll
            for (int c = 0; c < 16; c++) {
                float4 d0 = dc4[c * 2], d1 = dc4[c * 2 + 1];
                float yc = yy[c];
                r[0] = fmaf(yc, d0.x, r[0]); r[1] = fmaf(yc, d0.y, r[1]);
                r[2] = fmaf(yc, d0.z, r[2]); r[3] = fmaf(yc, d0.w, r[3]);
                r[4] = fmaf(yc, d1.x, r[4]); r[5] = fmaf(yc, d1.y, r[5]);
                r[6] = fmaf(yc, d1.z, r[6]); r[7] = fmaf(yc, d1.w, r[7]);
            }
            float* pb = sP1 + al * (8 * 129) + m;
            #pragma unroll
            for (int h = 0; h < 8; h++) pb[h * 129] = r[h];
        }
    }
    __syncthreads();
    // stage 2: m-contraction, 4 st per thread
    {
        int al = t >> 7, r = t & 127, st4 = r >> 3, h = r & 7;
        if (al < ab) {
            float a0r = 0.f, a1r = 0.f, a2r = 0.f, a3r = 0.f;
            const float* p1r = sP1 + al * (8 * 129) + h * 129;
            const float4* ds4 = reinterpret_cast<const float4*>(sDs);
            #pragma unroll 4
            for (int m = 0; m < 128; m++) {
                float4 d = ds4[m * 16 + st4];
                float pv = p1r[m];
                a0r = fmaf(pv, d.x, a0r); a1r = fmaf(pv, d.y, a1r);
                a2r = fmaf(pv, d.z, a2r); a3r = fmaf(pv, d.w, a3r);
            }
            size_t base = ((size_t)(p * AD + a0 + al)) * 512;
            p2[base + (st4 * 4 + 0) * 8 + h] = a0r;
            p2[base + (st4 * 4 + 1) * 8 + h] = a1r;
            p2[base + (st4 * 4 + 2) * 8 + h] = a2r;
            p2[base + (st4 * 4 + 3) * 8 + h] = a3r;
        }
    }
}

// kB: P2b[p,a',col] = sum_a Ga[a',a]*P2[p,a,col] - AdjX1[p,a',col]
// grid (256, 8): col-eighths of 64.  dyn smem: sP2[98*64] | sGa[98*128 padded]
#define KB_SP2  0
#define KB_SGA  (AD * 64)
#define KB_SMEM ((AD*64 + AD*128) * 4)        // 75,264 B
__global__ void __launch_bounds__(512, 2)
kB_gram(const float* __restrict__ p2, const float* __restrict__ adjx,
        float* __restrict__ p2b) {
    extern __shared__ float sm[];
    float* sP2 = sm + KB_SP2;
    float* sGa = sm + KB_SGA;
    int p = blockIdx.x, cq = blockIdx.y;
    int t = threadIdx.x;
    for (int i = t; i < AD * 64; i += 512) {
        int a = i >> 6, c = i & 63;
        sP2[i] = p2[((size_t)(p * AD + a)) * 512 + cq * 64 + c];
    }
    for (int i = t; i < AD * 128; i += 512) {
        int rr = i >> 7, cc = i & 127;
        sGa[i] = (cc < AD) ? g_Ga[rr * AD + cc] : 0.f;
    }
    __syncthreads();
    int col = t & 63, ag = t >> 6;          // 8 groups of 16 a'
    int abase = ag * 16;
    float acc[16];
    #pragma unroll
    for (int j = 0; j < 16; j++) acc[j] = 0.f;
    for (int a = 0; a < AD; a++) {
        float v = sP2[(a << 6) + col];
        const float4* gr = reinterpret_cast<const float4*>(sGa + (a << 7) + abase);
        #pragma unroll
        for (int k = 0; k < 4; k++) {
            float4 gg = gr[k];
            acc[k*4+0] = fmaf(v, gg.x, acc[k*4+0]);
            acc[k*4+1] = fmaf(v, gg.y, acc[k*4+1]);
            acc[k*4+2] = fmaf(v, gg.z, acc[k*4+2]);
            acc[k*4+3] = fmaf(v, gg.w, acc[k*4+3]);
        }
    }
    #pragma unroll
    for (int j = 0; j < 16; j++) {
        int ap = abase + j;
        if (ap < AD) {
            size_t o = ((size_t)(p * AD + ap)) * 512 + cq * 64 + col;
            p2b[o] = acc[j] - adjx[o];
        }
    }
}

// kC: from T=P2b: Q2[m,h] = sum_st Ds[m,st] T[st,h]; g[c] = sum_h Q2 Dc[c,h];
//     zn = soft(y - step*g, thr); y = zn + mom*(zn - z); z = zn
// dyn smem: sTmp[128*65] | sDsT[64*132] | sT[4*512] | sQ2[4*8*129] | sDc[128]
#define KC_STMP  0
#define KC_SDST  (128 * 65)
#define KC_ST    (KC_SDST + 64 * 132)
#define KC_SQ2   (KC_ST + 4 * 512)
#define KC_SDC   (KC_SQ2 + 4 * 8 * 129)
#define KC_SMEM  ((KC_SDC + 128) * 4)         // 92,288 B
__global__ void __launch_bounds__(512, 2)
kC_update(const float* __restrict__ tin, const float* __restrict__ ds,
          const float* __restrict__ dc, float scale, float mom, int first) {
    extern __shared__ float sm[];
    float* sTmp = sm + KC_STMP;
    float* sDsT = sm + KC_SDST;
    float* sT   = sm + KC_ST;
    float* sQ2  = sm + KC_SQ2;
    float* sDc  = sm + KC_SDC;
    int p = blockIdx.x, a0 = blockIdx.y * 4;
    int ab = min(4, AD - a0);
    int t = threadIdx.x;
    for (int i = t; i < MD * STD; i += 512) { int m = i >> 6, st = i & 63; sTmp[m * 65 + st] = ds[i]; }
    if (t < 128) sDc[t] = dc[t];
    for (int i = t; i < ab * 512; i += 512) {
        int al = i >> 9, j = i & 511;
        sT[al * 512 + j] = scale * tin[((size_t)(p * AD + a0 + al)) * 512 + j];
    }
    __syncthreads();
    for (int i = t; i < STD * MD; i += 512) {
        int st = i >> 7, m = i & 127;
        sDsT[st * 132 + m] = sTmp[m * 65 + st];
    }
    __syncthreads();
    // stage 1: st-contraction, 8 m per thread
    {
        int al = t >> 7, r = t & 127, m8 = r >> 3, h = r & 7;
        if (al < ab) {
            float acc[8];
            #pragma unroll
            for (int j = 0; j < 8; j++) acc[j] = 0.f;
            const float* tp = sT + al * 512 + h;
            #pragma unroll 4
            for (int st = 0; st < 64; st++) {
                const float4* dd = reinterpret_cast<const float4*>(sDsT + st * 132 + m8 * 8);
                float4 d0 = dd[0], d1 = dd[1];
                float tv = tp[st * 8];
                acc[0] = fmaf(tv, d0.x, acc[0]); acc[1] = fmaf(tv, d0.y, acc[1]);
                acc[2] = fmaf(tv, d0.z, acc[2]); acc[3] = fmaf(tv, d0.w, acc[3]);
                acc[4] = fmaf(tv, d1.x, acc[4]); acc[5] = fmaf(tv, d1.y, acc[5]);
                acc[6] = fmaf(tv, d1.z, acc[6]); acc[7] = fmaf(tv, d1.w, acc[7]);
            }
            float* qb = sQ2 + al * (8 * 129) + h * 129 + m8 * 8;
            #pragma unroll
            for (int j = 0; j < 8; j++) qb[j] = acc[j];
        }
    }
    __syncthreads();
    // stage 2: c-contraction + FISTA update
    {
        int al = t >> 7, m = t & 127;
        if (al < ab) {
            float q[8];
            const float* qb = sQ2 + al * (8 * 129) + m;
            #pragma unroll
            for (int h = 0; h < 8; h++) q[h] = qb[h * 129];
            float step = g_step, thr = g_thr;
            size_t zoff = ((size_t)(p * AD + a0 + al)) * 2048 + m * 16;
            float4* zp = reinterpret_cast<float4*>(g_Z + zoff);
            float4* yp = reinterpret_cast<float4*>(g_Y + zoff);
            const float4* dc4 = reinterpret_cast<const float4*>(sDc);
            #pragma unroll
            for (int jj = 0; jj < 4; jj++) {
                float4 yv, zv;
                if (first) { yv = make_float4(0.f,0.f,0.f,0.f); zv = yv; }
                else       { yv = yp[jj]; zv = zp[jj]; }
                float yin[4] = {yv.x, yv.y, yv.z, yv.w};
                float zin[4] = {zv.x, zv.y, zv.z, zv.w};
                float znv[4], ynv[4];
                #pragma unroll
                for (int k = 0; k < 4; k++) {
                    int c = jj * 4 + k;
                    float4 d0 = dc4[c * 2], d1 = dc4[c * 2 + 1];
                    float g = q[0]*d0.x + q[1]*d0.y + q[2]*d0.z + q[3]*d0.w
                            + q[4]*d1.x + q[5]*d1.y + q[6]*d1.z + q[7]*d1.w;
                    float v = yin[k] - step * g;
                    float av = fabsf(v) - thr;
                    float zn = (av > 0.f) ? copysignf(av, v) : 0.f;
                    znv[k] = zn;
                    ynv[k] = zn + mom * (zn - zin[k]);
                }
                zp[jj] = make_float4(znv[0], znv[1], znv[2], znv[3]);
                yp[jj] = make_float4(ynv[0], ynv[1], ynv[2], ynv[3]);
            }
        }
    }
}

// ---------------- host launch ----------------
extern "C" void kernel_launch(void* const* d_in, const int* in_sizes, int n_in,
                              void* d_out, int out_size) {
    const float* x  = (const float*)d_in[0];
    const float* da = (const float*)d_in[1];
    const float* ds = (const float*)d_in[2];
    const float* dc = (const float*)d_in[3];
    float* out = (float*)d_out;

    void *pGa, *pGs, *pGc, *pv, *pw, *pZ, *pY, *pP2, *pP2b, *pAdjX1;
    cudaGetSymbolAddress(&pGa, g_Ga);
    cudaGetSymbolAddress(&pGs, g_Gs);
    cudaGetSymbolAddress(&pGc, g_Gc);
    cudaGetSymbolAddress(&pv,  g_v);
    cudaGetSymbolAddress(&pw,  g_w);
    cudaGetSymbolAddress(&pZ,  g_Z);
    cudaGetSymbolAddress(&pY,  g_Y);
    cudaGetSymbolAddress(&pP2, g_P2);
    cudaGetSymbolAddress(&pP2b, g_P2b);
    cudaGetSymbolAddress(&pAdjX1, g_AdjX1);

    size_t smem_adj = (size_t)(UVD * 512 + AD * UVD) * sizeof(float);
    cudaFuncSetAttribute(k_adj_a,  cudaFuncAttributeMaxDynamicSharedMemorySize, (int)smem_adj);
    cudaFuncSetAttribute(kA_recon, cudaFuncAttributeMaxDynamicSharedMemorySize, KA_SMEM);
    cudaFuncSetAttribute(kB_gram,  cudaFuncAttributeMaxDynamicSharedMemorySize, KB_SMEM);
    cudaFuncSetAttribute(kC_update,cudaFuncAttributeMaxDynamicSharedMemorySize, KC_SMEM);

    // Gram matrices (Ga for kB; Gs/Gc for the power iteration)
    k_gram<<<(9604  + 255) / 256, 256>>>(da, (float*)pGa, 98, 49);
    k_gram<<<(16384 + 255) / 256, 256>>>(ds, (float*)pGs, 128, 64);
    k_gram<<<1, 256>>>(dc, (float*)pGc, 16, 8);

    // v0 + power iteration for L
    k_v0<<<(VSZ + 255) / 256, 256>>>();
    k_norm<<<1, 1024>>>((const float*)pv, VSZ);
    k_scale<<<VSZ / 256, 256>>>((const float*)pv, (float*)pv, VSZ, 0.f);
    for (int it = 0; it < 10; ++it) {
        k_eig_c<<<(AD * MD + 255) / 256, 256>>>();
        k_eig_s<<<VSZ / 256, 256>>>();
        k_eig_a<<<VSZ / 256, 256>>>();
        k_norm<<<1, 1024>>>((const float*)pw, VSZ);
        k_scale<<<VSZ / 256, 256>>>((const float*)pw, (float*)pv, VSZ, 1e-12f);
    }
    k_finalize<<<1, 1>>>();

    // AdjX1 = Da^T x  (once)
    k_adj_a<<<256, 512, smem_adj>>>(x, (float*)pAdjX1, da);

    // momentum schedule (data-independent)
    float mom[15]; float tmom = 1.f;
    for (int i = 0; i < 15; i++) {
        float tn = (1.f + sqrtf(1.f + 4.f * tmom * tmom)) * 0.5f;
        mom[i] = (tmom - 1.f) / tn;
        tmom = tn;
    }

    dim3 gAC(256, 25);   // 4 a per block (last block 2)
    dim3 gB(256, 8);     // 64-col slices

    // iteration 1: y=z=0 -> gradient = -AdjX1 path
    kC_update<<<gAC, 512, KC_SMEM>>>((const float*)pAdjX1, ds, dc, -1.f, mom[0], 1);

    // iterations 2..15
    for (int it = 1; it < 15; ++it) {
        kA_recon<<<gAC, 512, KA_SMEM>>>((const float*)pY, ds, dc, (float*)pP2);
        kB_gram<<<gB, 512, KB_SMEM>>>((const float*)pP2, (const float*)pAdjX1, (float*)pP2b);
        kC_update<<<gAC, 512, KC_SMEM>>>((const float*)pP2b, ds, dc, 1.f, mom[it], 0);
    }

    // final reconstruction from z
    kA_recon<<<gAC, 512, KA_SMEM>>>((const float*)pZ, ds, dc, (float*)pP2);
    k_recon_a<<<256, 512>>>((const float*)pP2, out, da);
}